// round 10
// baseline (speedup 1.0000x reference)
#include <cuda_runtime.h>
#include <math.h>

#define N_ROWS 1024
#define M_ROWS 1024
#define DD 256
#define QS 268     // score-kernel shared stride

__device__ float g_q[N_ROWS * DD];
__device__ float g_k[M_ROWS * DD];
__device__ float g_e[N_ROWS * M_ROWS];         // unnormalized exp of scores
__device__ float g_rowpart[32 * N_ROWS];       // per-mtile rowsum partials
__device__ float g_ctxpart[4 * N_ROWS * DD];   // K-split raw ctx partials
__device__ float g_ctx[N_ROWS * DD];
__device__ float g_sppart[4 * N_ROWS];         // per-dtile sp partials
__device__ float g_scratch;

typedef unsigned long long ull;

__device__ __forceinline__ float tanh_fast(float x) {
    float y;
    asm("tanh.approx.f32 %0, %1;" : "=f"(y) : "f"(x));
    return y;
}
__device__ __forceinline__ ull pack_dup(float x) {
    ull r;
    unsigned u = __float_as_uint(x);
    asm("mov.b64 %0, {%1, %2};" : "=l"(r) : "r"(u), "r"(u));
    return r;
}
__device__ __forceinline__ ull fma2(ull a, ull b, ull c) {
    ull d;
    asm("fma.rn.f32x2 %0, %1, %2, %3;" : "=l"(d) : "l"(a), "l"(b), "l"(c));
    return d;
}
__device__ __forceinline__ void unpack2(ull v, float& lo, float& hi) {
    unsigned a, b;
    asm("mov.b64 {%0, %1}, %2;" : "=r"(a), "=r"(b) : "l"(v));
    lo = __uint_as_float(a);
    hi = __uint_as_float(b);
}
__device__ __forceinline__ void cp16(unsigned dst, const void* src) {
    asm volatile("cp.async.cg.shared.global [%0], [%1], 16;" :: "r"(dst), "l"(src));
}
__device__ __forceinline__ void cp_commit() {
    asm volatile("cp.async.commit_group;" ::: "memory");
}
template <int N>
__device__ __forceinline__ void cp_wait() {
    asm volatile("cp.async.wait_group %0;" :: "n"(N) : "memory");
}

// ---------------------------------------------------------------------------
// GEMM (NT): out[n,j] = bias[j] + sum_d A[n,d]*B[j,d].  z=0: q ; z=1: k
// ---------------------------------------------------------------------------
__global__ void gemm_qk_kernel(const float* __restrict__ fr,
                               const float* __restrict__ frp,
                               const float* __restrict__ Ww,
                               const float* __restrict__ Wb,
                               const float* __restrict__ Wpw,
                               const float* __restrict__ Wpb,
                               int z) {
    const float* __restrict__ A    = z ? frp : fr;
    const float* __restrict__ B    = z ? Wpw : Ww;
    const float* __restrict__ bias = z ? Wpb : Wb;
    float* out = z ? g_k : g_q;

    const int bn = blockIdx.x * 64;
    const int bj = blockIdx.y * 64;
    const int tid = threadIdx.x;
    const int tx = tid & 15, ty = tid >> 4;

    __shared__ float As[64][33];
    __shared__ float Bs[64][33];

    float acc[4][4];
#pragma unroll
    for (int i = 0; i < 4; i++)
#pragma unroll
        for (int j = 0; j < 4; j++) acc[i][j] = 0.f;

    for (int k0 = 0; k0 < DD; k0 += 32) {
#pragma unroll
        for (int it = 0; it < 2; it++) {
            int idx = tid + it * 256;
            int row = idx >> 3;
            int c4  = (idx & 7) * 4;
            float4 va = *(const float4*)&A[(bn + row) * DD + k0 + c4];
            As[row][c4 + 0] = va.x; As[row][c4 + 1] = va.y;
            As[row][c4 + 2] = va.z; As[row][c4 + 3] = va.w;
            float4 vb = *(const float4*)&B[(bj + row) * DD + k0 + c4];
            Bs[row][c4 + 0] = vb.x; Bs[row][c4 + 1] = vb.y;
            Bs[row][c4 + 2] = vb.z; Bs[row][c4 + 3] = vb.w;
        }
        __syncthreads();
#pragma unroll 8
        for (int kk = 0; kk < 32; kk++) {
            float a[4], b[4];
#pragma unroll
            for (int i = 0; i < 4; i++) a[i] = As[ty * 4 + i][kk];
#pragma unroll
            for (int j = 0; j < 4; j++) b[j] = Bs[tx * 4 + j][kk];
#pragma unroll
            for (int i = 0; i < 4; i++)
#pragma unroll
                for (int j = 0; j < 4; j++) acc[i][j] += a[i] * b[j];
        }
        __syncthreads();
    }

    float4 bv = *(const float4*)&bias[bj + tx * 4];
#pragma unroll
    for (int i = 0; i < 4; i++) {
        float4 o;
        o.x = acc[i][0] + bv.x;
        o.y = acc[i][1] + bv.y;
        o.z = acc[i][2] + bv.z;
        o.w = acc[i][3] + bv.w;
        *(float4*)&out[(bn + ty * 4 + i) * DD + bj + tx * 4] = o;
    }
}

// ---------------------------------------------------------------------------
// L2 warm / profiling-alignment kernel (puts score_kernel at capture idx 3).
// ---------------------------------------------------------------------------
__global__ void warm_kernel(const float* __restrict__ p) {
    float acc = 0.f;
    for (int i = blockIdx.x * blockDim.x + threadIdx.x; i < M_ROWS * DD;
         i += gridDim.x * blockDim.x)
        acc += p[i];
    if (acc == 1.2345e-38f) g_scratch = acc;   // never true; keeps loads alive
}

// ---------------------------------------------------------------------------
// Scores + exp: e[n,m] = exp2(sum_d (w[d]*log2e)*tanh(q[n,d]+k[m,d]))
// (no-max softmax: |s| <= sum|w| <= 16 -> fp32-safe; w_b cancels).
// grid (32 m-tiles, 16 n-tiles), block 256. Per-thread 4n x 2m over D in SMEM
// -> ZERO shuffles in mainloop; runs at the MUFU tanh floor.
// Also writes per-(mtile,row) rowsum partials (deterministic, no atomics).
// ---------------------------------------------------------------------------
__global__ void score_kernel(const float* __restrict__ ww) {
    extern __shared__ float smem[];
    float* qs = smem;
    float* ks = smem + 64 * QS;
    float* ws = smem + 96 * QS;

    const int tid = threadIdx.x;
    const int mt = blockIdx.x;
    const int bm = mt * 32;
    const int bn = blockIdx.y * 64;

#pragma unroll
    for (int it = 0; it < 16; it++) {
        int idx = tid + it * 256;
        int row = idx >> 6;
        int c4  = (idx & 63) * 4;
        *(float4*)&qs[row * QS + c4] = *(const float4*)&g_q[(bn + row) * DD + c4];
    }
#pragma unroll
    for (int it = 0; it < 8; it++) {
        int idx = tid + it * 256;
        int row = idx >> 6;
        int c4  = (idx & 63) * 4;
        *(float4*)&ks[row * QS + c4] = *(const float4*)&g_k[(bm + row) * DD + c4];
    }
    if (tid < 64) {
        const float L2E = 1.44269504f;
        float4 w4 = *(const float4*)&ww[tid * 4];
        w4.x *= L2E; w4.y *= L2E; w4.z *= L2E; w4.w *= L2E;
        *(float4*)&ws[tid * 4] = w4;
    }
    __syncthreads();

    const int tx = tid & 15, ty = tid >> 4;
    const float* qp = &qs[(ty * 4) * QS];
    const float* kp = &ks[(tx * 2) * QS];

    float acc[4][2];
#pragma unroll
    for (int i = 0; i < 4; i++) { acc[i][0] = 0.f; acc[i][1] = 0.f; }

#pragma unroll 4
    for (int d4 = 0; d4 < 64; d4++) {
        float4 wv = *(const float4*)&ws[d4 * 4];
        float4 qv[4], kv[2];
#pragma unroll
        for (int i = 0; i < 4; i++) qv[i] = *(const float4*)&qp[i * QS + d4 * 4];
#pragma unroll
        for (int j = 0; j < 2; j++) kv[j] = *(const float4*)&kp[j * QS + d4 * 4];
#pragma unroll
        for (int i = 0; i < 4; i++)
#pragma unroll
            for (int j = 0; j < 2; j++) {
                acc[i][j] += wv.x * tanh_fast(qv[i].x + kv[j].x);
                acc[i][j] += wv.y * tanh_fast(qv[i].y + kv[j].y);
                acc[i][j] += wv.z * tanh_fast(qv[i].z + kv[j].z);
                acc[i][j] += wv.w * tanh_fast(qv[i].w + kv[j].w);
            }
    }

    // Epilogue: exp2, store e, and per-row partial sums (half-warp owns a row)
#pragma unroll
    for (int i = 0; i < 4; i++) {
        float e0 = exp2f(acc[i][0]);
        float e1 = exp2f(acc[i][1]);
        int n = bn + ty * 4 + i;
        *(float2*)&g_e[n * M_ROWS + bm + tx * 2] = make_float2(e0, e1);
        float rs = e0 + e1;
        rs += __shfl_xor_sync(0xffffffffu, rs, 1);
        rs += __shfl_xor_sync(0xffffffffu, rs, 2);
        rs += __shfl_xor_sync(0xffffffffu, rs, 4);
        rs += __shfl_xor_sync(0xffffffffu, rs, 8);
        if (tx == 0) g_rowpart[mt * N_ROWS + n] = rs;
    }
}

// ---------------------------------------------------------------------------
// K-split context GEMM: ctxpart[z] = E[:, z*256:(z+1)*256] @ frp[z*256:...].
// grid (32 n-tiles, 4 d-tiles, 4 K-slices) = 512 blocks, 256 threads.
// Block tile 32n x 64d x 256m (4 chunks of 64), cp.async double-buffered.
// Thread tile 2n x 4d, FFMA2 inner loop. Raw partials (normalize in fold).
// ---------------------------------------------------------------------------
#define ES_F (32 * 68)          // one E stage: 32 rows x 68 stride
#define FS_F (64 * 68)          // one F stage: 64 rows x 68 stride
#define CG_ES_OFF 0
#define CG_FS_OFF (2 * ES_F)
#define CG_SMEM_FLOATS (2 * ES_F + 2 * FS_F)

__global__ __launch_bounds__(256)
void ctx_gemm_kernel(const float* __restrict__ frp) {
    extern __shared__ float sm[];
    float* Es = sm + CG_ES_OFF;     // [2][32][68]
    float* Fs = sm + CG_FS_OFF;     // [2][64][68]

    const int tid = threadIdx.x, tx = tid & 15, ty = tid >> 4;
    const int bn = blockIdx.x * 32, bd = blockIdx.y * 64;
    const int mz = blockIdx.z * 256;
    const unsigned es_u = (unsigned)__cvta_generic_to_shared(Es);
    const unsigned fs_u = (unsigned)__cvta_generic_to_shared(Fs);

    // Prefetch chunks 0, 1
#pragma unroll
    for (int c = 0; c < 2; c++) {
        const int m0 = mz + c * 64;
#pragma unroll
        for (int j = 0; j < 2; j++) {            // E: 512 float4
            int idx = tid + j * 256;
            int row = idx >> 4;
            int c4 = (idx & 15) * 4;
            cp16(es_u + (unsigned)((c * ES_F + row * 68 + c4) * 4),
                 g_e + (bn + row) * M_ROWS + m0 + c4);
        }
#pragma unroll
        for (int j = 0; j < 4; j++) {            // F: 1024 float4
            int idx = tid + j * 256;
            int row = idx >> 4;
            int c4 = (idx & 15) * 4;
            cp16(fs_u + (unsigned)((c * FS_F + row * 68 + c4) * 4),
                 frp + (m0 + row) * DD + bd + c4);
        }
        cp_commit();
    }

    ull acc2[2][2];
    acc2[0][0] = 0ull; acc2[0][1] = 0ull;
    acc2[1][0] = 0ull; acc2[1][1] = 0ull;

    const int r0 = ty * 2;

    for (int c = 0; c < 4; c++) {
        if (c == 3) cp_wait<0>(); else cp_wait<1>();
        __syncthreads();
        const float* E = Es + (c & 1) * ES_F;
        const float* F = Fs + (c & 1) * FS_F;
#pragma unroll 4
        for (int g = 0; g < 16; g++) {
            float4 ea = *(const float4*)&E[r0 * 68 + g * 4];
            float4 eb = *(const float4*)&E[(r0 + 1) * 68 + g * 4];
            const float eav[4] = {ea.x, ea.y, ea.z, ea.w};
            const float ebv[4] = {eb.x, eb.y, eb.z, eb.w};
#pragma unroll
            for (int u = 0; u < 4; u++) {
                ulonglong2 f = *(const ulonglong2*)&F[(g * 4 + u) * 68 + tx * 4];
                ull a0 = pack_dup(eav[u]);
                ull a1 = pack_dup(ebv[u]);
                acc2[0][0] = fma2(a0, f.x, acc2[0][0]);
                acc2[0][1] = fma2(a0, f.y, acc2[0][1]);
                acc2[1][0] = fma2(a1, f.x, acc2[1][0]);
                acc2[1][1] = fma2(a1, f.y, acc2[1][1]);
            }
        }
        __syncthreads();
        if (c + 2 < 4) {
            const int buf = c & 1;
            const int m0 = mz + (c + 2) * 64;
#pragma unroll
            for (int j = 0; j < 2; j++) {
                int idx = tid + j * 256;
                int row = idx >> 4;
                int c4 = (idx & 15) * 4;
                cp16(es_u + (unsigned)((buf * ES_F + row * 68 + c4) * 4),
                     g_e + (bn + row) * M_ROWS + m0 + c4);
            }
#pragma unroll
            for (int j = 0; j < 4; j++) {
                int idx = tid + j * 256;
                int row = idx >> 4;
                int c4 = (idx & 15) * 4;
                cp16(fs_u + (unsigned)((buf * FS_F + row * 68 + c4) * 4),
                     frp + (m0 + row) * DD + bd + c4);
            }
            cp_commit();
        }
    }

    // Write raw partials
    float* outp = g_ctxpart + blockIdx.z * (N_ROWS * DD);
#pragma unroll
    for (int r = 0; r < 2; r++) {
        int n = bn + r0 + r;
        float4 v;
        unpack2(acc2[r][0], v.x, v.y);
        unpack2(acc2[r][1], v.z, v.w);
        *(float4*)&outp[n * DD + bd + tx * 4] = v;
    }
}

// ---------------------------------------------------------------------------
// Fold: ctx = (sum_z ctxpart[z]) / rowsum ; sp partials = ctx . wp_w.
// grid (32 n-tiles, 4 d-tiles), 256 threads.
// ---------------------------------------------------------------------------
__global__ void fold_kernel(const float* __restrict__ wpw) {
    __shared__ float sinv[32];

    const int tid = threadIdx.x, tx = tid & 15, ty = tid >> 4;
    const int bn = blockIdx.x * 32, bd = blockIdx.y * 64;

    if (tid < 32) {
        float s = 0.f;
#pragma unroll
        for (int p = 0; p < 32; p++) s += g_rowpart[p * N_ROWS + bn + tid];
        sinv[tid] = 1.f / s;
    }
    __syncthreads();

    float4 wv4 = *(const float4*)&wpw[bd + tx * 4];
    const int r0 = ty * 2;
#pragma unroll
    for (int r = 0; r < 2; r++) {
        int n = bn + r0 + r;
        int off = n * DD + bd + tx * 4;
        float4 v0 = *(const float4*)&g_ctxpart[off];
        float4 v1 = *(const float4*)&g_ctxpart[N_ROWS * DD + off];
        float4 v2 = *(const float4*)&g_ctxpart[2 * N_ROWS * DD + off];
        float4 v3 = *(const float4*)&g_ctxpart[3 * N_ROWS * DD + off];
        float is = sinv[r0 + r];
        float4 v;
        v.x = (v0.x + v1.x + v2.x + v3.x) * is;
        v.y = (v0.y + v1.y + v2.y + v3.y) * is;
        v.z = (v0.z + v1.z + v2.z + v3.z) * is;
        v.w = (v0.w + v1.w + v2.w + v3.w) * is;
        *(float4*)&g_ctx[off] = v;
        float pv = v.x * wv4.x + v.y * wv4.y + v.z * wv4.z + v.w * wv4.w;
        pv += __shfl_xor_sync(0xffffffffu, pv, 1);
        pv += __shfl_xor_sync(0xffffffffu, pv, 2);
        pv += __shfl_xor_sync(0xffffffffu, pv, 4);
        pv += __shfl_xor_sync(0xffffffffu, pv, 8);
        if (tx == 0) g_sppart[blockIdx.y * N_ROWS + n] = pv;
    }
}

// ---------------------------------------------------------------------------
// Final: sp = sum of d-tile partials; softmax over n (wp_b cancels); pool.
// 1 block, 1024 threads.
// ---------------------------------------------------------------------------
__global__ void final_kernel(float* __restrict__ out) {
    __shared__ float sp[1024];
    __shared__ float red[32];
    __shared__ float part[16 * 256];

    const int tid = threadIdx.x, lane = tid & 31, wid = tid >> 5;

    float v = g_sppart[tid] + g_sppart[N_ROWS + tid]
            + g_sppart[2 * N_ROWS + tid] + g_sppart[3 * N_ROWS + tid];
    float mx = v;
#pragma unroll
    for (int o = 16; o; o >>= 1) mx = fmaxf(mx, __shfl_xor_sync(0xffffffffu, mx, o));
    if (lane == 0) red[wid] = mx;
    __syncthreads();
    if (tid < 32) {
        float m2 = red[lane];
#pragma unroll
        for (int o = 16; o; o >>= 1) m2 = fmaxf(m2, __shfl_xor_sync(0xffffffffu, m2, o));
        if (lane == 0) red[0] = m2;
    }
    __syncthreads();
    float gmx = red[0];
    __syncthreads();

    float e = __expf(v - gmx);
    float s = e;
#pragma unroll
    for (int o = 16; o; o >>= 1) s += __shfl_xor_sync(0xffffffffu, s, o);
    if (lane == 0) red[wid] = s;
    __syncthreads();
    if (tid < 32) {
        float s2 = red[lane];
#pragma unroll
        for (int o = 16; o; o >>= 1) s2 += __shfl_xor_sync(0xffffffffu, s2, o);
        if (lane == 0) red[0] = s2;
    }
    __syncthreads();
    sp[tid] = e / red[0];
    __syncthreads();

    const int p = tid >> 6, dg = tid & 63;
    const int d0 = dg * 4;
    float4 acc = make_float4(0.f, 0.f, 0.f, 0.f);
#pragma unroll 4
    for (int t = 0; t < 64; t++) {
        int n = p * 64 + t;
        float a = sp[n];
        float4 f = *(const float4*)&g_ctx[n * DD + d0];
        acc.x += a * f.x; acc.y += a * f.y;
        acc.z += a * f.z; acc.w += a * f.w;
    }
    *(float4*)&part[p * 256 + d0] = acc;
    __syncthreads();

    if (tid < 256) {
        float r = 0.f;
#pragma unroll
        for (int bb = 0; bb < 16; bb++) r += part[bb * 256 + tid];
        out[tid] = r;
    }
}

// ---------------------------------------------------------------------------
extern "C" void kernel_launch(void* const* d_in, const int* in_sizes, int n_in,
                              void* d_out, int out_size) {
    const float* fr  = (const float*)d_in[0];
    const float* frp = (const float*)d_in[1];
    const float* Ww  = (const float*)d_in[2];
    const float* Wb  = (const float*)d_in[3];
    const float* Wpw = (const float*)d_in[4];
    const float* Wpb = (const float*)d_in[5];
    const float* ww  = (const float*)d_in[6];
    // d_in[7] = w_b, d_in[9] = wp_b: scalar biases cancel inside softmax — unused.
    const float* wpw = (const float*)d_in[8];
    float* out = (float*)d_out;

    const int score_smem = (96 * QS + 256) * (int)sizeof(float);   // ~103.9KB
    const int cg_smem    = CG_SMEM_FLOATS * (int)sizeof(float);    // ~52.2KB
    cudaFuncSetAttribute(score_kernel,
                         cudaFuncAttributeMaxDynamicSharedMemorySize, score_smem);
    cudaFuncSetAttribute(ctx_gemm_kernel,
                         cudaFuncAttributeMaxDynamicSharedMemorySize, cg_smem);

    gemm_qk_kernel<<<dim3(16, 4), 256>>>(fr, frp, Ww, Wb, Wpw, Wpb, 0);  // idx 0
    gemm_qk_kernel<<<dim3(16, 4), 256>>>(fr, frp, Ww, Wb, Wpw, Wpb, 1);  // idx 1
    warm_kernel<<<148, 256>>>(frp);                                      // idx 2
    score_kernel<<<dim3(32, 16), 256, score_smem>>>(ww);                 // idx 3 (profiled)
    ctx_gemm_kernel<<<dim3(32, 4, 4), 256, cg_smem>>>(frp);              // idx 4
    fold_kernel<<<dim3(32, 4), 256>>>(wpw);                              // idx 5
    final_kernel<<<1, 1024>>>(out);                                      // idx 6
}

// round 11
// speedup vs baseline: 1.0803x; 1.0803x over previous
#include <cuda_runtime.h>
#include <math.h>

#define N_ROWS 1024
#define M_ROWS 1024
#define DD 256
#define QS 268     // score-kernel shared stride

__device__ float g_q[N_ROWS * DD];
__device__ float g_k[M_ROWS * DD];
__device__ float g_e2[N_ROWS * 2 * M_ROWS];    // exp(scores), duplicated {e,e}
__device__ float g_rowpart[32 * N_ROWS];       // per-mtile rowsum partials
__device__ float g_sinv[N_ROWS];               // 1/rowsum
__device__ float g_ctxpart[2 * N_ROWS * DD];   // K-split raw ctx partials
__device__ float g_ctx[N_ROWS * DD];
__device__ float g_sppart[4 * N_ROWS];         // per-dtile sp partials

typedef unsigned long long ull;

__device__ __forceinline__ float tanh_fast(float x) {
    float y;
    asm("tanh.approx.f32 %0, %1;" : "=f"(y) : "f"(x));
    return y;
}
__device__ __forceinline__ ull fma2(ull a, ull b, ull c) {
    ull d;
    asm("fma.rn.f32x2 %0, %1, %2, %3;" : "=l"(d) : "l"(a), "l"(b), "l"(c));
    return d;
}
__device__ __forceinline__ void unpack2(ull v, float& lo, float& hi) {
    unsigned a, b;
    asm("mov.b64 {%0, %1}, %2;" : "=r"(a), "=r"(b) : "l"(v));
    lo = __uint_as_float(a);
    hi = __uint_as_float(b);
}
__device__ __forceinline__ void cp16(unsigned dst, const void* src) {
    asm volatile("cp.async.cg.shared.global [%0], [%1], 16;" :: "r"(dst), "l"(src));
}
__device__ __forceinline__ void cp_commit() {
    asm volatile("cp.async.commit_group;" ::: "memory");
}
template <int N>
__device__ __forceinline__ void cp_wait() {
    asm volatile("cp.async.wait_group %0;" :: "n"(N) : "memory");
}

// ---------------------------------------------------------------------------
// GEMM (NT): out[n,j] = bias[j] + sum_d A[n,d]*B[j,d].  z=0: q ; z=1: k
// grid (16, 4, 2), block 256.
// ---------------------------------------------------------------------------
__global__ void gemm_qk_kernel(const float* __restrict__ fr,
                               const float* __restrict__ frp,
                               const float* __restrict__ Ww,
                               const float* __restrict__ Wb,
                               const float* __restrict__ Wpw,
                               const float* __restrict__ Wpb) {
    const int z = blockIdx.z;
    const float* __restrict__ A    = z ? frp : fr;
    const float* __restrict__ B    = z ? Wpw : Ww;
    const float* __restrict__ bias = z ? Wpb : Wb;
    float* out = z ? g_k : g_q;

    const int bn = blockIdx.x * 64;
    const int bj = blockIdx.y * 64;
    const int tid = threadIdx.x;
    const int tx = tid & 15, ty = tid >> 4;

    __shared__ float As[64][33];
    __shared__ float Bs[64][33];

    float acc[4][4];
#pragma unroll
    for (int i = 0; i < 4; i++)
#pragma unroll
        for (int j = 0; j < 4; j++) acc[i][j] = 0.f;

    for (int k0 = 0; k0 < DD; k0 += 32) {
#pragma unroll
        for (int it = 0; it < 2; it++) {
            int idx = tid + it * 256;
            int row = idx >> 3;
            int c4  = (idx & 7) * 4;
            float4 va = *(const float4*)&A[(bn + row) * DD + k0 + c4];
            As[row][c4 + 0] = va.x; As[row][c4 + 1] = va.y;
            As[row][c4 + 2] = va.z; As[row][c4 + 3] = va.w;
            float4 vb = *(const float4*)&B[(bj + row) * DD + k0 + c4];
            Bs[row][c4 + 0] = vb.x; Bs[row][c4 + 1] = vb.y;
            Bs[row][c4 + 2] = vb.z; Bs[row][c4 + 3] = vb.w;
        }
        __syncthreads();
#pragma unroll 8
        for (int kk = 0; kk < 32; kk++) {
            float a[4], b[4];
#pragma unroll
            for (int i = 0; i < 4; i++) a[i] = As[ty * 4 + i][kk];
#pragma unroll
            for (int j = 0; j < 4; j++) b[j] = Bs[tx * 4 + j][kk];
#pragma unroll
            for (int i = 0; i < 4; i++)
#pragma unroll
                for (int j = 0; j < 4; j++) acc[i][j] += a[i] * b[j];
        }
        __syncthreads();
    }

    float4 bv = *(const float4*)&bias[bj + tx * 4];
#pragma unroll
    for (int i = 0; i < 4; i++) {
        float4 o;
        o.x = acc[i][0] + bv.x;
        o.y = acc[i][1] + bv.y;
        o.z = acc[i][2] + bv.z;
        o.w = acc[i][3] + bv.w;
        *(float4*)&out[(bn + ty * 4 + i) * DD + bj + tx * 4] = o;
    }
}

// ---------------------------------------------------------------------------
// Scores + exp: e[n,m] = exp2(sum_d (w[d]*log2e)*tanh(q[n,d]+k[m,d]))
// (no-max softmax: |s| <= sum|w| <= 16 -> fp32-safe; w_b cancels).
// Stores e DUPLICATED as {e,e} pairs (FFMA2-ready operands for ctx GEMM).
// grid (32 m-tiles, 16 n-tiles), block 256. ZERO shuffles in mainloop;
// verified at the MUFU tanh floor (R10 profile).
// ---------------------------------------------------------------------------
__global__ void score_kernel(const float* __restrict__ ww) {
    extern __shared__ float smem[];
    float* qs = smem;
    float* ks = smem + 64 * QS;
    float* ws = smem + 96 * QS;

    const int tid = threadIdx.x;
    const int mt = blockIdx.x;
    const int bm = mt * 32;
    const int bn = blockIdx.y * 64;

#pragma unroll
    for (int it = 0; it < 16; it++) {
        int idx = tid + it * 256;
        int row = idx >> 6;
        int c4  = (idx & 63) * 4;
        *(float4*)&qs[row * QS + c4] = *(const float4*)&g_q[(bn + row) * DD + c4];
    }
#pragma unroll
    for (int it = 0; it < 8; it++) {
        int idx = tid + it * 256;
        int row = idx >> 6;
        int c4  = (idx & 63) * 4;
        *(float4*)&ks[row * QS + c4] = *(const float4*)&g_k[(bm + row) * DD + c4];
    }
    if (tid < 64) {
        const float L2E = 1.44269504f;
        float4 w4 = *(const float4*)&ww[tid * 4];
        w4.x *= L2E; w4.y *= L2E; w4.z *= L2E; w4.w *= L2E;
        *(float4*)&ws[tid * 4] = w4;
    }
    __syncthreads();

    const int tx = tid & 15, ty = tid >> 4;
    const float* qp = &qs[(ty * 4) * QS];
    const float* kp = &ks[(tx * 2) * QS];

    float acc[4][2];
#pragma unroll
    for (int i = 0; i < 4; i++) { acc[i][0] = 0.f; acc[i][1] = 0.f; }

#pragma unroll 4
    for (int d4 = 0; d4 < 64; d4++) {
        float4 wv = *(const float4*)&ws[d4 * 4];
        float4 qv[4], kv[2];
#pragma unroll
        for (int i = 0; i < 4; i++) qv[i] = *(const float4*)&qp[i * QS + d4 * 4];
#pragma unroll
        for (int j = 0; j < 2; j++) kv[j] = *(const float4*)&kp[j * QS + d4 * 4];
#pragma unroll
        for (int i = 0; i < 4; i++)
#pragma unroll
            for (int j = 0; j < 2; j++) {
                acc[i][j] += wv.x * tanh_fast(qv[i].x + kv[j].x);
                acc[i][j] += wv.y * tanh_fast(qv[i].y + kv[j].y);
                acc[i][j] += wv.z * tanh_fast(qv[i].z + kv[j].z);
                acc[i][j] += wv.w * tanh_fast(qv[i].w + kv[j].w);
            }
    }

    // Epilogue: exp2, store duplicated {e0,e0,e1,e1}, per-row partial sums
#pragma unroll
    for (int i = 0; i < 4; i++) {
        float e0 = exp2f(acc[i][0]);
        float e1 = exp2f(acc[i][1]);
        int n = bn + ty * 4 + i;
        *(float4*)&g_e2[n * (2 * M_ROWS) + (bm + tx * 2) * 2] =
            make_float4(e0, e0, e1, e1);
        float rs = e0 + e1;
        rs += __shfl_xor_sync(0xffffffffu, rs, 1);
        rs += __shfl_xor_sync(0xffffffffu, rs, 2);
        rs += __shfl_xor_sync(0xffffffffu, rs, 4);
        rs += __shfl_xor_sync(0xffffffffu, rs, 8);
        if (tx == 0) g_rowpart[mt * N_ROWS + n] = rs;
    }
}

// ---------------------------------------------------------------------------
// Rowsum inverse prep (also aligns ctx_gemm to capture idx 3). grid 4 x 256.
// ---------------------------------------------------------------------------
__global__ void sinv_prep_kernel() {
    const int n = blockIdx.x * 256 + threadIdx.x;
    float s = 0.f;
#pragma unroll
    for (int p = 0; p < 32; p++) s += g_rowpart[p * N_ROWS + n];
    g_sinv[n] = 1.f / s;
}

// ---------------------------------------------------------------------------
// K-split context GEMM: ctxpart[z] = E[:, z*512:(z+1)*512] @ frp[z*512:...].
// grid (32 n-tiles, 4 d-tiles, 2 K-slices) = 256 blocks, 256 threads
// -> exactly one wave at 2 blocks/SM. Block tile 32n x 64d x 512m (8 chunks
// of 64), cp.async double-buffered. Thread tile 2n x 4d. E arrives from
// g_e2 pre-duplicated -> LDS.128 yields two FFMA2 a-operands, zero MOVs.
// ---------------------------------------------------------------------------
#define ES_F (32 * 132)         // one E stage: 32 rows x 132 stride (128 data)
#define FS_F (64 * 68)          // one F stage: 64 rows x 68 stride
#define CG_SMEM_FLOATS (2 * ES_F + 2 * FS_F)

__global__ __launch_bounds__(256)
void ctx_gemm_kernel(const float* __restrict__ frp) {
    extern __shared__ float sm[];
    float* Es = sm;                  // [2][32][132]
    float* Fs = sm + 2 * ES_F;       // [2][64][68]

    const int tid = threadIdx.x, tx = tid & 15, ty = tid >> 4;
    const int bn = blockIdx.x * 32, bd = blockIdx.y * 64;
    const int mz = blockIdx.z * 512;
    const unsigned es_u = (unsigned)__cvta_generic_to_shared(Es);
    const unsigned fs_u = (unsigned)__cvta_generic_to_shared(Fs);

    // Prefetch chunks 0, 1
#pragma unroll
    for (int c = 0; c < 2; c++) {
        const int m0 = mz + c * 64;
#pragma unroll
        for (int j = 0; j < 4; j++) {            // E: 1024 float4 (dup data)
            int idx = tid + j * 256;
            int row = idx >> 5;                  // 0..31
            int c4 = (idx & 31) * 4;             // 0..124
            cp16(es_u + (unsigned)((c * ES_F + row * 132 + c4) * 4),
                 g_e2 + (bn + row) * (2 * M_ROWS) + m0 * 2 + c4);
        }
#pragma unroll
        for (int j = 0; j < 4; j++) {            // F: 1024 float4
            int idx = tid + j * 256;
            int row = idx >> 4;                  // 0..63
            int c4 = (idx & 15) * 4;             // 0..60
            cp16(fs_u + (unsigned)((c * FS_F + row * 68 + c4) * 4),
                 frp + (m0 + row) * DD + bd + c4);
        }
        cp_commit();
    }

    ull acc2[2][2];
    acc2[0][0] = 0ull; acc2[0][1] = 0ull;
    acc2[1][0] = 0ull; acc2[1][1] = 0ull;

    const int r0 = ty * 2;

    for (int c = 0; c < 8; c++) {
        if (c == 7) cp_wait<0>(); else cp_wait<1>();
        __syncthreads();
        const float* E = Es + (c & 1) * ES_F;
        const float* F = Fs + (c & 1) * FS_F;
#pragma unroll 4
        for (int g = 0; g < 16; g++) {
            // Pre-duplicated pairs: .x = {e(m),e(m)}, .y = {e(m+1),e(m+1)}
            ulonglong2 ea01 = *(const ulonglong2*)&E[r0 * 132 + g * 8];
            ulonglong2 ea23 = *(const ulonglong2*)&E[r0 * 132 + g * 8 + 4];
            ulonglong2 eb01 = *(const ulonglong2*)&E[(r0 + 1) * 132 + g * 8];
            ulonglong2 eb23 = *(const ulonglong2*)&E[(r0 + 1) * 132 + g * 8 + 4];
            const ull ea[4] = {ea01.x, ea01.y, ea23.x, ea23.y};
            const ull eb[4] = {eb01.x, eb01.y, eb23.x, eb23.y};
#pragma unroll
            for (int u = 0; u < 4; u++) {
                ulonglong2 f = *(const ulonglong2*)&F[(g * 4 + u) * 68 + tx * 4];
                acc2[0][0] = fma2(ea[u], f.x, acc2[0][0]);
                acc2[0][1] = fma2(ea[u], f.y, acc2[0][1]);
                acc2[1][0] = fma2(eb[u], f.x, acc2[1][0]);
                acc2[1][1] = fma2(eb[u], f.y, acc2[1][1]);
            }
        }
        __syncthreads();
        if (c + 2 < 8) {
            const int buf = c & 1;
            const int m0 = mz + (c + 2) * 64;
#pragma unroll
            for (int j = 0; j < 4; j++) {
                int idx = tid + j * 256;
                int row = idx >> 5;
                int c4 = (idx & 31) * 4;
                cp16(es_u + (unsigned)((buf * ES_F + row * 132 + c4) * 4),
                     g_e2 + (bn + row) * (2 * M_ROWS) + m0 * 2 + c4);
            }
#pragma unroll
            for (int j = 0; j < 4; j++) {
                int idx = tid + j * 256;
                int row = idx >> 4;
                int c4 = (idx & 15) * 4;
                cp16(fs_u + (unsigned)((buf * FS_F + row * 68 + c4) * 4),
                     frp + (m0 + row) * DD + bd + c4);
            }
            cp_commit();
        }
    }

    // Write raw partials
    float* outp = g_ctxpart + blockIdx.z * (N_ROWS * DD);
#pragma unroll
    for (int r = 0; r < 2; r++) {
        int n = bn + r0 + r;
        float4 v;
        unpack2(acc2[r][0], v.x, v.y);
        unpack2(acc2[r][1], v.z, v.w);
        *(float4*)&outp[n * DD + bd + tx * 4] = v;
    }
}

// ---------------------------------------------------------------------------
// Fold: ctx = (ctxpart[0]+ctxpart[1]) * sinv ; sp partials = ctx . wp_w.
// grid (32 n-tiles, 4 d-tiles), 256 threads.
// ---------------------------------------------------------------------------
__global__ void fold_kernel(const float* __restrict__ wpw) {
    const int tid = threadIdx.x, tx = tid & 15, ty = tid >> 4;
    const int bn = blockIdx.x * 32, bd = blockIdx.y * 64;

    float4 wv4 = *(const float4*)&wpw[bd + tx * 4];
    const int r0 = ty * 2;
#pragma unroll
    for (int r = 0; r < 2; r++) {
        int n = bn + r0 + r;
        int off = n * DD + bd + tx * 4;
        float4 v0 = *(const float4*)&g_ctxpart[off];
        float4 v1 = *(const float4*)&g_ctxpart[N_ROWS * DD + off];
        float is = g_sinv[n];
        float4 v;
        v.x = (v0.x + v1.x) * is;
        v.y = (v0.y + v1.y) * is;
        v.z = (v0.z + v1.z) * is;
        v.w = (v0.w + v1.w) * is;
        *(float4*)&g_ctx[off] = v;
        float pv = v.x * wv4.x + v.y * wv4.y + v.z * wv4.z + v.w * wv4.w;
        pv += __shfl_xor_sync(0xffffffffu, pv, 1);
        pv += __shfl_xor_sync(0xffffffffu, pv, 2);
        pv += __shfl_xor_sync(0xffffffffu, pv, 4);
        pv += __shfl_xor_sync(0xffffffffu, pv, 8);
        if (tx == 0) g_sppart[blockIdx.y * N_ROWS + n] = pv;
    }
}

// ---------------------------------------------------------------------------
// Final: sp = sum of d-tile partials; softmax over n (wp_b cancels); pool.
// 1 block, 1024 threads.
// ---------------------------------------------------------------------------
__global__ void final_kernel(float* __restrict__ out) {
    __shared__ float sp[1024];
    __shared__ float red[32];
    __shared__ float part[16 * 256];

    const int tid = threadIdx.x, lane = tid & 31, wid = tid >> 5;

    float v = g_sppart[tid] + g_sppart[N_ROWS + tid]
            + g_sppart[2 * N_ROWS + tid] + g_sppart[3 * N_ROWS + tid];
    float mx = v;
#pragma unroll
    for (int o = 16; o; o >>= 1) mx = fmaxf(mx, __shfl_xor_sync(0xffffffffu, mx, o));
    if (lane == 0) red[wid] = mx;
    __syncthreads();
    if (tid < 32) {
        float m2 = red[lane];
#pragma unroll
        for (int o = 16; o; o >>= 1) m2 = fmaxf(m2, __shfl_xor_sync(0xffffffffu, m2, o));
        if (lane == 0) red[0] = m2;
    }
    __syncthreads();
    float gmx = red[0];
    __syncthreads();

    float e = __expf(v - gmx);
    float s = e;
#pragma unroll
    for (int o = 16; o; o >>= 1) s += __shfl_xor_sync(0xffffffffu, s, o);
    if (lane == 0) red[wid] = s;
    __syncthreads();
    if (tid < 32) {
        float s2 = red[lane];
#pragma unroll
        for (int o = 16; o; o >>= 1) s2 += __shfl_xor_sync(0xffffffffu, s2, o);
        if (lane == 0) red[0] = s2;
    }
    __syncthreads();
    sp[tid] = e / red[0];
    __syncthreads();

    const int p = tid >> 6, dg = tid & 63;
    const int d0 = dg * 4;
    float4 acc = make_float4(0.f, 0.f, 0.f, 0.f);
#pragma unroll 4
    for (int t = 0; t < 64; t++) {
        int n = p * 64 + t;
        float a = sp[n];
        float4 f = *(const float4*)&g_ctx[n * DD + d0];
        acc.x += a * f.x; acc.y += a * f.y;
        acc.z += a * f.z; acc.w += a * f.w;
    }
    *(float4*)&part[p * 256 + d0] = acc;
    __syncthreads();

    if (tid < 256) {
        float r = 0.f;
#pragma unroll
        for (int bb = 0; bb < 16; bb++) r += part[bb * 256 + tid];
        out[tid] = r;
    }
}

// ---------------------------------------------------------------------------
extern "C" void kernel_launch(void* const* d_in, const int* in_sizes, int n_in,
                              void* d_out, int out_size) {
    const float* fr  = (const float*)d_in[0];
    const float* frp = (const float*)d_in[1];
    const float* Ww  = (const float*)d_in[2];
    const float* Wb  = (const float*)d_in[3];
    const float* Wpw = (const float*)d_in[4];
    const float* Wpb = (const float*)d_in[5];
    const float* ww  = (const float*)d_in[6];
    // d_in[7] = w_b, d_in[9] = wp_b: scalar biases cancel inside softmax — unused.
    const float* wpw = (const float*)d_in[8];
    float* out = (float*)d_out;

    const int score_smem = (96 * QS + 256) * (int)sizeof(float);   // ~103.9KB
    const int cg_smem    = CG_SMEM_FLOATS * (int)sizeof(float);    // ~68.6KB
    cudaFuncSetAttribute(score_kernel,
                         cudaFuncAttributeMaxDynamicSharedMemorySize, score_smem);
    cudaFuncSetAttribute(ctx_gemm_kernel,
                         cudaFuncAttributeMaxDynamicSharedMemorySize, cg_smem);

    gemm_qk_kernel<<<dim3(16, 4, 2), 256>>>(fr, frp, Ww, Wb, Wpw, Wpb);  // idx 0
    score_kernel<<<dim3(32, 16), 256, score_smem>>>(ww);                 // idx 1
    sinv_prep_kernel<<<4, 256>>>();                                      // idx 2
    ctx_gemm_kernel<<<dim3(32, 4, 2), 256, cg_smem>>>(frp);              // idx 3 (profiled)
    fold_kernel<<<dim3(32, 4), 256>>>(wpw);                              // idx 4
    final_kernel<<<1, 1024>>>(out);                                      // idx 5
}

// round 12
// speedup vs baseline: 1.1927x; 1.1040x over previous
#include <cuda_runtime.h>
#include <math.h>

#define N_ROWS 1024
#define M_ROWS 1024
#define DD 256
#define QS 268     // score-kernel shared stride

__device__ float g_q[N_ROWS * DD];
__device__ float g_k[M_ROWS * DD];
__device__ float g_e[N_ROWS * M_ROWS];         // unnormalized exp of scores
__device__ float g_frpT[DD * M_ROWS];          // frp transposed [d-perm][m]
__device__ float g_rowpart[32 * N_ROWS];       // per-mtile rowsum partials
__device__ float g_sinv[N_ROWS];               // 1/rowsum
__device__ float g_ctxpart[8 * N_ROWS * DD];   // K-split raw ctx partials
__device__ float g_ctx[N_ROWS * DD];
__device__ float g_sppart[4 * N_ROWS];         // per-dtile sp partials

typedef unsigned long long ull;

__device__ __forceinline__ float tanh_fast(float x) {
    float y;
    asm("tanh.approx.f32 %0, %1;" : "=f"(y) : "f"(x));
    return y;
}
__device__ __forceinline__ ull fma2(ull a, ull b, ull c) {
    ull d;
    asm("fma.rn.f32x2 %0, %1, %2, %3;" : "=l"(d) : "l"(a), "l"(b), "l"(c));
    return d;
}
__device__ __forceinline__ void unpack2(ull v, float& lo, float& hi) {
    unsigned a, b;
    asm("mov.b64 {%0, %1}, %2;" : "=r"(a), "=r"(b) : "l"(v));
    lo = __uint_as_float(a);
    hi = __uint_as_float(b);
}
__device__ __forceinline__ void cp16(unsigned dst, const void* src) {
    asm volatile("cp.async.cg.shared.global [%0], [%1], 16;" :: "r"(dst), "l"(src));
}
__device__ __forceinline__ void cp_commit() {
    asm volatile("cp.async.commit_group;" ::: "memory");
}
template <int N>
__device__ __forceinline__ void cp_wait() {
    asm volatile("cp.async.wait_group %0;" :: "n"(N) : "memory");
}

// ---------------------------------------------------------------------------
// GEMM (NT): out[n,j] = bias[j] + sum_d A[n,d]*B[j,d].  z=0: q ; z=1: k
// grid (16, 4, 2), block 256.
// ---------------------------------------------------------------------------
__global__ void gemm_qk_kernel(const float* __restrict__ fr,
                               const float* __restrict__ frp,
                               const float* __restrict__ Ww,
                               const float* __restrict__ Wb,
                               const float* __restrict__ Wpw,
                               const float* __restrict__ Wpb) {
    const int z = blockIdx.z;
    const float* __restrict__ A    = z ? frp : fr;
    const float* __restrict__ B    = z ? Wpw : Ww;
    const float* __restrict__ bias = z ? Wpb : Wb;
    float* out = z ? g_k : g_q;

    const int bn = blockIdx.x * 64;
    const int bj = blockIdx.y * 64;
    const int tid = threadIdx.x;
    const int tx = tid & 15, ty = tid >> 4;

    __shared__ float As[64][33];
    __shared__ float Bs[64][33];

    float acc[4][4];
#pragma unroll
    for (int i = 0; i < 4; i++)
#pragma unroll
        for (int j = 0; j < 4; j++) acc[i][j] = 0.f;

    for (int k0 = 0; k0 < DD; k0 += 32) {
#pragma unroll
        for (int it = 0; it < 2; it++) {
            int idx = tid + it * 256;
            int row = idx >> 3;
            int c4  = (idx & 7) * 4;
            float4 va = *(const float4*)&A[(bn + row) * DD + k0 + c4];
            As[row][c4 + 0] = va.x; As[row][c4 + 1] = va.y;
            As[row][c4 + 2] = va.z; As[row][c4 + 3] = va.w;
            float4 vb = *(const float4*)&B[(bj + row) * DD + k0 + c4];
            Bs[row][c4 + 0] = vb.x; Bs[row][c4 + 1] = vb.y;
            Bs[row][c4 + 2] = vb.z; Bs[row][c4 + 3] = vb.w;
        }
        __syncthreads();
#pragma unroll 8
        for (int kk = 0; kk < 32; kk++) {
            float a[4], b[4];
#pragma unroll
            for (int i = 0; i < 4; i++) a[i] = As[ty * 4 + i][kk];
#pragma unroll
            for (int j = 0; j < 4; j++) b[j] = Bs[tx * 4 + j][kk];
#pragma unroll
            for (int i = 0; i < 4; i++)
#pragma unroll
                for (int j = 0; j < 4; j++) acc[i][j] += a[i] * b[j];
        }
        __syncthreads();
    }

    float4 bv = *(const float4*)&bias[bj + tx * 4];
#pragma unroll
    for (int i = 0; i < 4; i++) {
        float4 o;
        o.x = acc[i][0] + bv.x;
        o.y = acc[i][1] + bv.y;
        o.z = acc[i][2] + bv.z;
        o.w = acc[i][3] + bv.w;
        *(float4*)&out[(bn + ty * 4 + i) * DD + bj + tx * 4] = o;
    }
}

// ---------------------------------------------------------------------------
// Scores + exp: e[n,m] = exp2(sum_d (w[d]*log2e)*tanh(q[n,d]+k[m,d]))
// (no-max softmax: |s| <= sum|w| <= 16 -> fp32-safe; w_b cancels).
// grid (32 m-tiles, 16 n-tiles), block 256. ZERO shuffles in mainloop;
// verified at the MUFU tanh floor (R10 profile: 72us).
// ---------------------------------------------------------------------------
__global__ void score_kernel(const float* __restrict__ ww) {
    extern __shared__ float smem[];
    float* qs = smem;
    float* ks = smem + 64 * QS;
    float* ws = smem + 96 * QS;

    const int tid = threadIdx.x;
    const int mt = blockIdx.x;
    const int bm = mt * 32;
    const int bn = blockIdx.y * 64;

#pragma unroll
    for (int it = 0; it < 16; it++) {
        int idx = tid + it * 256;
        int row = idx >> 6;
        int c4  = (idx & 63) * 4;
        *(float4*)&qs[row * QS + c4] = *(const float4*)&g_q[(bn + row) * DD + c4];
    }
#pragma unroll
    for (int it = 0; it < 8; it++) {
        int idx = tid + it * 256;
        int row = idx >> 6;
        int c4  = (idx & 63) * 4;
        *(float4*)&ks[row * QS + c4] = *(const float4*)&g_k[(bm + row) * DD + c4];
    }
    if (tid < 64) {
        const float L2E = 1.44269504f;
        float4 w4 = *(const float4*)&ww[tid * 4];
        w4.x *= L2E; w4.y *= L2E; w4.z *= L2E; w4.w *= L2E;
        *(float4*)&ws[tid * 4] = w4;
    }
    __syncthreads();

    const int tx = tid & 15, ty = tid >> 4;
    const float* qp = &qs[(ty * 4) * QS];
    const float* kp = &ks[(tx * 2) * QS];

    float acc[4][2];
#pragma unroll
    for (int i = 0; i < 4; i++) { acc[i][0] = 0.f; acc[i][1] = 0.f; }

#pragma unroll 4
    for (int d4 = 0; d4 < 64; d4++) {
        float4 wv = *(const float4*)&ws[d4 * 4];
        float4 qv[4], kv[2];
#pragma unroll
        for (int i = 0; i < 4; i++) qv[i] = *(const float4*)&qp[i * QS + d4 * 4];
#pragma unroll
        for (int j = 0; j < 2; j++) kv[j] = *(const float4*)&kp[j * QS + d4 * 4];
#pragma unroll
        for (int i = 0; i < 4; i++)
#pragma unroll
            for (int j = 0; j < 2; j++) {
                acc[i][j] += wv.x * tanh_fast(qv[i].x + kv[j].x);
                acc[i][j] += wv.y * tanh_fast(qv[i].y + kv[j].y);
                acc[i][j] += wv.z * tanh_fast(qv[i].z + kv[j].z);
                acc[i][j] += wv.w * tanh_fast(qv[i].w + kv[j].w);
            }
    }

    // Epilogue: exp2, store e, per-row partial sums (half-warp owns a row)
#pragma unroll
    for (int i = 0; i < 4; i++) {
        float e0 = exp2f(acc[i][0]);
        float e1 = exp2f(acc[i][1]);
        int n = bn + ty * 4 + i;
        *(float2*)&g_e[n * M_ROWS + bm + tx * 2] = make_float2(e0, e1);
        float rs = e0 + e1;
        rs += __shfl_xor_sync(0xffffffffu, rs, 1);
        rs += __shfl_xor_sync(0xffffffffu, rs, 2);
        rs += __shfl_xor_sync(0xffffffffu, rs, 4);
        rs += __shfl_xor_sync(0xffffffffu, rs, 8);
        if (tx == 0) g_rowpart[mt * N_ROWS + n] = rs;
    }
}

// ---------------------------------------------------------------------------
// Prep: (a) transpose frp -> frpT[d-permuted][m] (row perm: within each
// 128-d tile, row = (d&7)*16 + (d>>3) so ctx F-reads are bank-spread);
// (b) rowsum inverses.  grid 260: blocks 0..255 transpose, 256..259 sinv.
// ---------------------------------------------------------------------------
__global__ void prep_kernel(const float* __restrict__ frp) {
    const int b = blockIdx.x;
    const int tid = threadIdx.x;
    if (b < 256) {
        __shared__ float t[32][33];
        const int bm = (b >> 3) * 32;       // m-tile
        const int bd32 = (b & 7) * 32;      // d-tile
        {
            int row = tid >> 3;             // m within tile
            int c4 = (tid & 7) * 4;         // d within tile
            float4 v = *(const float4*)&frp[(bm + row) * DD + bd32 + c4];
            t[row][c4 + 0] = v.x; t[row][c4 + 1] = v.y;
            t[row][c4 + 2] = v.z; t[row][c4 + 3] = v.w;
        }
        __syncthreads();
        {
            int dd = tid >> 3;              // d within tile (0..31)
            int mi4 = (tid & 7) * 4;        // m within tile
            float4 o;
            o.x = t[mi4 + 0][dd];
            o.y = t[mi4 + 1][dd];
            o.z = t[mi4 + 2][dd];
            o.w = t[mi4 + 3][dd];
            int d = bd32 + dd;
            int tile = d >> 7, dt = d & 127;
            int row_g = tile * 128 + ((dt & 7) << 4) + (dt >> 3);
            *(float4*)&g_frpT[row_g * M_ROWS + bm + mi4] = o;
        }
    } else {
        const int n = (b - 256) * 256 + tid;
        float s = 0.f;
#pragma unroll
        for (int p = 0; p < 32; p++) s += g_rowpart[p * N_ROWS + n];
        g_sinv[n] = 1.f / s;
    }
}

// ---------------------------------------------------------------------------
// K-split context GEMM, m-paired FFMA2: acc{even,odd} += {e_m,e_m1}*{f_m,f_m1}.
// Both operands natural m-consecutive (E from g_e rows, F from g_frpT rows).
// grid (16 n-tiles, 2 d-tiles, 8 K-slices) = 256 blocks, 256 threads, 2/SM.
// Block tile 64n x 128d x 128m (single smem stage). Thread tile 4n x 8d.
// Crossbar cost: 12 LDS.128 per warp per 4 m (was 24) -> ~12us model.
// ---------------------------------------------------------------------------
#define EF 132                  // row stride (floats) for E and F stages
#define E_STAGE (64 * EF)       // 8448
#define F_STAGE (128 * EF)      // 16896
#define CG_SMEM_FLOATS (E_STAGE + F_STAGE)   // 25344 floats = 101376 B

__global__ __launch_bounds__(256, 2)
void ctx_gemm_kernel() {
    extern __shared__ float sm[];
    float* Es = sm;                  // [64][EF]
    float* Fs = sm + E_STAGE;        // [128][EF]  (d-rows permuted)

    const int tid = threadIdx.x, tx = tid & 15, ty = tid >> 4;
    const int bn = blockIdx.x * 64;
    const int bd = blockIdx.y * 128;
    const int mz = blockIdx.z * 128;
    const unsigned es_u = (unsigned)__cvta_generic_to_shared(Es);
    const unsigned fs_u = (unsigned)__cvta_generic_to_shared(Fs);

    // Stage E (64 x 128 floats) and F (128 x 128 floats)
#pragma unroll
    for (int j = 0; j < 8; j++) {            // E: 2048 float4
        int idx = tid + j * 256;
        int row = idx >> 5;                  // 0..63
        int c4 = (idx & 31) * 4;             // 0..124
        cp16(es_u + (unsigned)((row * EF + c4) * 4),
             g_e + (bn + row) * M_ROWS + mz + c4);
    }
#pragma unroll
    for (int j = 0; j < 16; j++) {           // F: 4096 float4
        int idx = tid + j * 256;
        int row = idx >> 5;                  // 0..127 (permuted d-row)
        int c4 = (idx & 31) * 4;
        cp16(fs_u + (unsigned)((row * EF + c4) * 4),
             g_frpT + (bd + row) * M_ROWS + mz + c4);
    }
    cp_commit();

    ull acc[4][8];
#pragma unroll
    for (int r = 0; r < 4; r++)
#pragma unroll
        for (int j = 0; j < 8; j++) acc[r][j] = 0ull;

    cp_wait<0>();
    __syncthreads();

    const float* Ep = Es + (ty * 4) * EF;
    const float* Fp = Fs + tx * EF;

#pragma unroll 2
    for (int mg = 0; mg < 32; mg++) {
        // E: 4 rows x 4 m  ({e_m0,e_m1},{e_m2,e_m3} pairs)
        ulonglong2 ea[4];
#pragma unroll
        for (int r = 0; r < 4; r++)
            ea[r] = *(const ulonglong2*)&Ep[r * EF + mg * 4];
        // F first 4 d-rows (j = 0..3 -> smem rows j*16+tx)
#pragma unroll
        for (int h = 0; h < 2; h++) {
            ulonglong2 fb[4];
#pragma unroll
            for (int j = 0; j < 4; j++)
                fb[j] = *(const ulonglong2*)&Fp[((h * 4 + j) * 16) * EF + mg * 4];
#pragma unroll
            for (int r = 0; r < 4; r++)
#pragma unroll
                for (int j = 0; j < 4; j++) {
                    acc[r][h * 4 + j] = fma2(ea[r].x, fb[j].x, acc[r][h * 4 + j]);
                    acc[r][h * 4 + j] = fma2(ea[r].y, fb[j].y, acc[r][h * 4 + j]);
                }
        }
    }

    // Epilogue: fold m-parity halves, write raw partials
    float* outp = g_ctxpart + blockIdx.z * (N_ROWS * DD);
#pragma unroll
    for (int r = 0; r < 4; r++) {
        int n = bn + ty * 4 + r;
        float4 v0, v1;
        float lo, hi;
        unpack2(acc[r][0], lo, hi); v0.x = lo + hi;
        unpack2(acc[r][1], lo, hi); v0.y = lo + hi;
        unpack2(acc[r][2], lo, hi); v0.z = lo + hi;
        unpack2(acc[r][3], lo, hi); v0.w = lo + hi;
        unpack2(acc[r][4], lo, hi); v1.x = lo + hi;
        unpack2(acc[r][5], lo, hi); v1.y = lo + hi;
        unpack2(acc[r][6], lo, hi); v1.z = lo + hi;
        unpack2(acc[r][7], lo, hi); v1.w = lo + hi;
        *(float4*)&outp[n * DD + bd + tx * 8] = v0;
        *(float4*)&outp[n * DD + bd + tx * 8 + 4] = v1;
    }
}

// ---------------------------------------------------------------------------
// Fold: ctx = (sum_z ctxpart[z]) * sinv ; sp partials = ctx . wp_w.
// grid (32 n-tiles, 4 d-tiles), 256 threads.
// ---------------------------------------------------------------------------
__global__ void fold_kernel(const float* __restrict__ wpw) {
    const int tid = threadIdx.x, tx = tid & 15, ty = tid >> 4;
    const int bn = blockIdx.x * 32, bd = blockIdx.y * 64;

    float4 wv4 = *(const float4*)&wpw[bd + tx * 4];
    const int r0 = ty * 2;
#pragma unroll
    for (int r = 0; r < 2; r++) {
        int n = bn + r0 + r;
        int off = n * DD + bd + tx * 4;
        float4 v = make_float4(0.f, 0.f, 0.f, 0.f);
#pragma unroll
        for (int z = 0; z < 8; z++) {
            float4 p = *(const float4*)&g_ctxpart[z * (N_ROWS * DD) + off];
            v.x += p.x; v.y += p.y; v.z += p.z; v.w += p.w;
        }
        float is = g_sinv[n];
        v.x *= is; v.y *= is; v.z *= is; v.w *= is;
        *(float4*)&g_ctx[off] = v;
        float pv = v.x * wv4.x + v.y * wv4.y + v.z * wv4.z + v.w * wv4.w;
        pv += __shfl_xor_sync(0xffffffffu, pv, 1);
        pv += __shfl_xor_sync(0xffffffffu, pv, 2);
        pv += __shfl_xor_sync(0xffffffffu, pv, 4);
        pv += __shfl_xor_sync(0xffffffffu, pv, 8);
        if (tx == 0) g_sppart[blockIdx.y * N_ROWS + n] = pv;
    }
}

// ---------------------------------------------------------------------------
// Final: sp = sum of d-tile partials; softmax over n (wp_b cancels); pool.
// 1 block, 1024 threads.
// ---------------------------------------------------------------------------
__global__ void final_kernel(float* __restrict__ out) {
    __shared__ float sp[1024];
    __shared__ float red[32];
    __shared__ float part[16 * 256];

    const int tid = threadIdx.x, lane = tid & 31, wid = tid >> 5;

    float v = g_sppart[tid] + g_sppart[N_ROWS + tid]
            + g_sppart[2 * N_ROWS + tid] + g_sppart[3 * N_ROWS + tid];
    float mx = v;
#pragma unroll
    for (int o = 16; o; o >>= 1) mx = fmaxf(mx, __shfl_xor_sync(0xffffffffu, mx, o));
    if (lane == 0) red[wid] = mx;
    __syncthreads();
    if (tid < 32) {
        float m2 = red[lane];
#pragma unroll
        for (int o = 16; o; o >>= 1) m2 = fmaxf(m2, __shfl_xor_sync(0xffffffffu, m2, o));
        if (lane == 0) red[0] = m2;
    }
    __syncthreads();
    float gmx = red[0];
    __syncthreads();

    float e = __expf(v - gmx);
    float s = e;
#pragma unroll
    for (int o = 16; o; o >>= 1) s += __shfl_xor_sync(0xffffffffu, s, o);
    if (lane == 0) red[wid] = s;
    __syncthreads();
    if (tid < 32) {
        float s2 = red[lane];
#pragma unroll
        for (int o = 16; o; o >>= 1) s2 += __shfl_xor_sync(0xffffffffu, s2, o);
        if (lane == 0) red[0] = s2;
    }
    __syncthreads();
    sp[tid] = e / red[0];
    __syncthreads();

    const int p = tid >> 6, dg = tid & 63;
    const int d0 = dg * 4;
    float4 acc = make_float4(0.f, 0.f, 0.f, 0.f);
#pragma unroll 4
    for (int t = 0; t < 64; t++) {
        int n = p * 64 + t;
        float a = sp[n];
        float4 f = *(const float4*)&g_ctx[n * DD + d0];
        acc.x += a * f.x; acc.y += a * f.y;
        acc.z += a * f.z; acc.w += a * f.w;
    }
    *(float4*)&part[p * 256 + d0] = acc;
    __syncthreads();

    if (tid < 256) {
        float r = 0.f;
#pragma unroll
        for (int bb = 0; bb < 16; bb++) r += part[bb * 256 + tid];
        out[tid] = r;
    }
}

// ---------------------------------------------------------------------------
extern "C" void kernel_launch(void* const* d_in, const int* in_sizes, int n_in,
                              void* d_out, int out_size) {
    const float* fr  = (const float*)d_in[0];
    const float* frp = (const float*)d_in[1];
    const float* Ww  = (const float*)d_in[2];
    const float* Wb  = (const float*)d_in[3];
    const float* Wpw = (const float*)d_in[4];
    const float* Wpb = (const float*)d_in[5];
    const float* ww  = (const float*)d_in[6];
    // d_in[7] = w_b, d_in[9] = wp_b: scalar biases cancel inside softmax — unused.
    const float* wpw = (const float*)d_in[8];
    float* out = (float*)d_out;

    const int score_smem = (96 * QS + 256) * (int)sizeof(float);   // ~103.9KB
    const int cg_smem    = CG_SMEM_FLOATS * (int)sizeof(float);    // ~101.4KB
    cudaFuncSetAttribute(score_kernel,
                         cudaFuncAttributeMaxDynamicSharedMemorySize, score_smem);
    cudaFuncSetAttribute(ctx_gemm_kernel,
                         cudaFuncAttributeMaxDynamicSharedMemorySize, cg_smem);

    gemm_qk_kernel<<<dim3(16, 4, 2), 256>>>(fr, frp, Ww, Wb, Wpw, Wpb);  // idx 0
    score_kernel<<<dim3(32, 16), 256, score_smem>>>(ww);                 // idx 1
    prep_kernel<<<260, 256>>>(frp);                                      // idx 2
    ctx_gemm_kernel<<<dim3(16, 2, 8), 256, cg_smem>>>();                 // idx 3 (profiled)
    fold_kernel<<<dim3(32, 4), 256>>>(wpw);                              // idx 4
    final_kernel<<<1, 1024>>>(out);                                      // idx 5
}